// round 3
// baseline (speedup 1.0000x reference)
#include <cuda_runtime.h>
#include <math.h>
#include <stdint.h>
#include <stddef.h>

#define NTOK 16384
#define CD   128
#define NB   65536          // B*N tokens
#define BMR  1024           // B*256 reduced tokens
#define KCONV 8192
#define CONVZ 16

static constexpr size_t SZ_TOK  = (size_t)NB * CD;          // 8388608
static constexpr size_t OFF_XA0 = 0;
static constexpr size_t OFF_XA1 = OFF_XA0 + SZ_TOK;
static constexpr size_t OFF_Q   = OFF_XA1 + SZ_TOK;
static constexpr size_t OFF_IM  = OFF_Q   + SZ_TOK;         // 1024*8192 == SZ_TOK
static constexpr size_t OFF_PART= OFF_IM  + SZ_TOK;         // 16*1024*128
static constexpr size_t OFF_WC  = OFF_PART+ (size_t)CONVZ*BMR*CD;
static constexpr size_t OFF_XILN= OFF_WC  + (size_t)CD*KCONV;
static constexpr size_t OFF_KVB = OFF_XILN+ (size_t)BMR*CD;
static constexpr size_t OFF_KH  = OFF_KVB + (size_t)BMR*2*CD;
static constexpr size_t OFF_VHT = OFF_KH  + (size_t)8*256*64;
static constexpr size_t OFF_SC  = OFF_VHT + (size_t)8*256*64;
static constexpr size_t OFF_H   = OFF_SC  + (size_t)8*NTOK*256;
static constexpr size_t OFF_S   = OFF_H   + SZ_TOK;
static constexpr size_t OFF_QKV = OFF_S   + SZ_TOK;
static constexpr size_t OFF_K1  = OFF_QKV + (size_t)NB*384;
static constexpr size_t OFF_V1  = OFF_K1  + SZ_TOK;
static constexpr size_t OFF_OB  = OFF_V1  + SZ_TOK;
static constexpr size_t OFF_N0  = OFF_OB  + SZ_TOK;
static constexpr size_t OFF_N1  = OFF_N0  + SZ_TOK;
static constexpr size_t OFF_CST = OFF_N1  + SZ_TOK;
static constexpr size_t POOL_SZ = OFF_CST + 256;

__device__ float g_pool[POOL_SZ];

__device__ __forceinline__ float geluf(float x) {
    return 0.5f * x * (1.0f + erff(x * 0.70710678118654752f));
}

// ---------------------------------------------------------------------------
// Generic fp32 GEMM: out[nrows x ncols] = A @ W^T (+bias, epilogue).
// W is (ncols, KD) row-major. Tile 64x64, BK=16, 256 threads, 4x4 microtile.
// AMODE: 0 plain A0 (row stride KD); 1 K-concat(A0,A1) each row stride CD;
//        2 elementwise A0*A1 (row stride KD).
// EPI: 0 +bias; 1 +bias,gelu; 2 +bias,+res; 3 raw partial at z-offset.
// ---------------------------------------------------------------------------
template<int KD, int KSTEPS, int AMODE, int EPI>
__global__ void __launch_bounds__(256) gemm_k(
    const float* __restrict__ A0, const float* __restrict__ A1,
    const float* __restrict__ W,  const float* __restrict__ bias,
    const float* __restrict__ res, float* __restrict__ out,
    int ncols, int nrows)
{
    __shared__ float As[16][64];
    __shared__ float Ws[16][64];
    const int tid = threadIdx.x, ty = tid >> 4, tx = tid & 15;
    const int row0 = blockIdx.x * 64, col0 = blockIdx.y * 64;
    const int kbase = blockIdx.z * (KSTEPS * 16);
    const int lrow = tid >> 2, lk4 = (tid & 3) * 4;
    float acc[4][4] = {};

    for (int kt = 0; kt < KSTEPS; ++kt) {
        const int kk = kbase + kt * 16 + lk4;
        float4 av, wv;
        if (AMODE == 0) {
            av = *(const float4*)(A0 + (size_t)(row0 + lrow) * KD + kk);
        } else if (AMODE == 1) {
            const float* src = (kk < CD) ? (A0 + (size_t)(row0 + lrow) * CD + kk)
                                         : (A1 + (size_t)(row0 + lrow) * CD + (kk - CD));
            av = *(const float4*)src;
        } else {
            float4 a = *(const float4*)(A0 + (size_t)(row0 + lrow) * KD + kk);
            float4 b = *(const float4*)(A1 + (size_t)(row0 + lrow) * KD + kk);
            av = make_float4(a.x*b.x, a.y*b.y, a.z*b.z, a.w*b.w);
        }
        wv = *(const float4*)(W + (size_t)(col0 + lrow) * KD + kk);
        As[lk4+0][lrow]=av.x; As[lk4+1][lrow]=av.y; As[lk4+2][lrow]=av.z; As[lk4+3][lrow]=av.w;
        Ws[lk4+0][lrow]=wv.x; Ws[lk4+1][lrow]=wv.y; Ws[lk4+2][lrow]=wv.z; Ws[lk4+3][lrow]=wv.w;
        __syncthreads();
        #pragma unroll
        for (int k = 0; k < 16; ++k) {
            float4 a = *(const float4*)&As[k][ty*4];
            float4 w = *(const float4*)&Ws[k][tx*4];
            acc[0][0]+=a.x*w.x; acc[0][1]+=a.x*w.y; acc[0][2]+=a.x*w.z; acc[0][3]+=a.x*w.w;
            acc[1][0]+=a.y*w.x; acc[1][1]+=a.y*w.y; acc[1][2]+=a.y*w.z; acc[1][3]+=a.y*w.w;
            acc[2][0]+=a.z*w.x; acc[2][1]+=a.z*w.y; acc[2][2]+=a.z*w.z; acc[2][3]+=a.z*w.w;
            acc[3][0]+=a.w*w.x; acc[3][1]+=a.w*w.y; acc[3][2]+=a.w*w.z; acc[3][3]+=a.w*w.w;
        }
        __syncthreads();
    }

    const int c0 = col0 + tx * 4;
    float4 b4 = make_float4(0.f,0.f,0.f,0.f);
    if (EPI != 3) b4 = *(const float4*)(bias + c0);
    #pragma unroll
    for (int i = 0; i < 4; ++i) {
        const int r = row0 + ty * 4 + i;
        float4 o4 = make_float4(acc[i][0]+b4.x, acc[i][1]+b4.y, acc[i][2]+b4.z, acc[i][3]+b4.w);
        if (EPI == 1) { o4.x=geluf(o4.x); o4.y=geluf(o4.y); o4.z=geluf(o4.z); o4.w=geluf(o4.w); }
        if (EPI == 2) {
            float4 rr = *(const float4*)(res + (size_t)r * ncols + c0);
            o4.x+=rr.x; o4.y+=rr.y; o4.z+=rr.z; o4.w+=rr.w;
        }
        float* dst = out + (EPI == 3 ? (size_t)blockIdx.z * nrows * ncols : (size_t)0)
                         + (size_t)r * ncols + c0;
        *(float4*)dst = o4;
    }
}

// im2col: row (b,ph,pw) -> K = (i*8+j)*128 + c
__global__ void im2col_k(const float* __restrict__ x, float* __restrict__ im)
{
    const int row = blockIdx.x;
    const int b = row >> 8, p = row & 255, ph = p >> 4, pw = p & 15;
    const float* xb = x + (size_t)b * NTOK * CD;
    float* dst = im + (size_t)row * KCONV;
    for (int k = threadIdx.x; k < KCONV; k += blockDim.x) {
        const int ij = k >> 7, c = k & 127, i = ij >> 3, j = ij & 7;
        dst[k] = xb[(size_t)((ph*8+i)*128 + pw*8+j) * CD + c];
    }
}

// conv weight reorder: wc[o][(i*8+j)*128+c] = sr_w[o][c][i][j]
__global__ void wconv_k(const float* __restrict__ w, float* __restrict__ wc)
{
    const int idx = blockIdx.x * blockDim.x + threadIdx.x;
    if (idx >= CD * KCONV) return;
    const int o = idx >> 13, k = idx & 8191, ij = k >> 7, c = k & 127;
    wc[idx] = w[(size_t)o * 8192 + c * 64 + ij];
}

// reduce conv K-partials + conv bias + layernorm
__global__ void convred_ln_k(const float* __restrict__ part, const float* __restrict__ sb,
                             const float* __restrict__ g, const float* __restrict__ be,
                             float* __restrict__ outp)
{
    const int row = blockIdx.x, c = threadIdx.x;  // 128 threads
    float v = sb[c];
    #pragma unroll
    for (int z = 0; z < CONVZ; ++z)
        v += part[(size_t)z * BMR * CD + (size_t)row * CD + c];
    __shared__ float red[4], red2[4];
    float s = v;
    #pragma unroll
    for (int o = 16; o; o >>= 1) s += __shfl_xor_sync(0xffffffffu, s, o);
    if ((c & 31) == 0) red[c >> 5] = s;
    __syncthreads();
    const float mean = (red[0]+red[1]+red[2]+red[3]) * (1.0f/CD);
    const float d = v - mean;
    float s2 = d * d;
    #pragma unroll
    for (int o = 16; o; o >>= 1) s2 += __shfl_xor_sync(0xffffffffu, s2, o);
    if ((c & 31) == 0) red2[c >> 5] = s2;
    __syncthreads();
    const float var = (red2[0]+red2[1]+red2[2]+red2[3]) * (1.0f/CD);
    outp[(size_t)row * CD + c] = d * rsqrtf(var + 1e-5f) * g[c] + be[c];
}

// split KV (BMR x 256) into per-(b,h) K [z][m][d] and V^T [z][d][m]
__global__ void kvsplit_k(const float* __restrict__ KVb, float* __restrict__ Kh,
                          float* __restrict__ Vt)
{
    const int idx = blockIdx.x * blockDim.x + threadIdx.x;
    if (idx >= 8*256*64) return;
    const int z = idx >> 14, r = idx & 16383, m = r >> 6, d = r & 63;
    const int b = z >> 1, h = z & 1;
    const float* src = KVb + (size_t)(b*256 + m) * 256 + h*64 + d;
    Kh[idx] = src[0];
    Vt[(size_t)z*16384 + d*256 + m] = src[128];
}

// SR scores: Sc[z][n][m] = 0.125 * sum_d q[b,n,h,d] * Kh[z][m][d]
__global__ void __launch_bounds__(256) sr_scores_k(const float* __restrict__ Q,
    const float* __restrict__ Kh, float* __restrict__ Sc)
{
    __shared__ float As[16][64]; __shared__ float Ws[16][64];
    const int tid = threadIdx.x, ty = tid >> 4, tx = tid & 15;
    const int row0 = blockIdx.x * 64, col0 = blockIdx.y * 64;
    const int z = blockIdx.z, b = z >> 1, h = z & 1;
    const int lrow = tid >> 2, lk4 = (tid & 3) * 4;
    float acc[4][4] = {};
    for (int kt = 0; kt < 4; ++kt) {
        const int kk = kt * 16 + lk4;
        float4 av = *(const float4*)(Q + (size_t)(b*NTOK + row0 + lrow) * 128 + h*64 + kk);
        float4 wv = *(const float4*)(Kh + (size_t)z*16384 + (size_t)(col0 + lrow)*64 + kk);
        As[lk4+0][lrow]=av.x; As[lk4+1][lrow]=av.y; As[lk4+2][lrow]=av.z; As[lk4+3][lrow]=av.w;
        Ws[lk4+0][lrow]=wv.x; Ws[lk4+1][lrow]=wv.y; Ws[lk4+2][lrow]=wv.z; Ws[lk4+3][lrow]=wv.w;
        __syncthreads();
        #pragma unroll
        for (int k = 0; k < 16; ++k) {
            float4 a = *(const float4*)&As[k][ty*4];
            float4 w = *(const float4*)&Ws[k][tx*4];
            acc[0][0]+=a.x*w.x; acc[0][1]+=a.x*w.y; acc[0][2]+=a.x*w.z; acc[0][3]+=a.x*w.w;
            acc[1][0]+=a.y*w.x; acc[1][1]+=a.y*w.y; acc[1][2]+=a.y*w.z; acc[1][3]+=a.y*w.w;
            acc[2][0]+=a.z*w.x; acc[2][1]+=a.z*w.y; acc[2][2]+=a.z*w.z; acc[2][3]+=a.z*w.w;
            acc[3][0]+=a.w*w.x; acc[3][1]+=a.w*w.y; acc[3][2]+=a.w*w.z; acc[3][3]+=a.w*w.w;
        }
        __syncthreads();
    }
    #pragma unroll
    for (int i = 0; i < 4; ++i) {
        float4 o4 = make_float4(acc[i][0]*0.125f, acc[i][1]*0.125f, acc[i][2]*0.125f, acc[i][3]*0.125f);
        *(float4*)(Sc + (size_t)z*4194304 + (size_t)(row0 + ty*4 + i)*256 + col0 + tx*4) = o4;
    }
}

// row softmax over 256, one warp per row
__global__ void softmax256_k(float* __restrict__ S)
{
    const int row = blockIdx.x * 8 + (threadIdx.x >> 5);
    const int lane = threadIdx.x & 31;
    float4* p = (float4*)(S + (size_t)row * 256 + lane * 8);
    float4 a = p[0], b = p[1];
    float mx = fmaxf(fmaxf(fmaxf(a.x,a.y),fmaxf(a.z,a.w)),
                     fmaxf(fmaxf(b.x,b.y),fmaxf(b.z,b.w)));
    #pragma unroll
    for (int o = 16; o; o >>= 1) mx = fmaxf(mx, __shfl_xor_sync(0xffffffffu, mx, o));
    a.x=__expf(a.x-mx); a.y=__expf(a.y-mx); a.z=__expf(a.z-mx); a.w=__expf(a.w-mx);
    b.x=__expf(b.x-mx); b.y=__expf(b.y-mx); b.z=__expf(b.z-mx); b.w=__expf(b.w-mx);
    float s = a.x+a.y+a.z+a.w+b.x+b.y+b.z+b.w;
    #pragma unroll
    for (int o = 16; o; o >>= 1) s += __shfl_xor_sync(0xffffffffu, s, o);
    const float inv = 1.0f / s;
    a.x*=inv; a.y*=inv; a.z*=inv; a.w*=inv; b.x*=inv; b.y*=inv; b.z*=inv; b.w*=inv;
    p[0] = a; p[1] = b;
}

// SR PV: xa[b,n,h*64+d] = sum_m P[z][n][m] * V[z][m][d]  (V^T staged)
__global__ void __launch_bounds__(256) sr_pv_k(const float* __restrict__ Sc,
    const float* __restrict__ Vt, float* __restrict__ XA)
{
    __shared__ float As[16][64]; __shared__ float Ws[16][64];
    const int tid = threadIdx.x, ty = tid >> 4, tx = tid & 15;
    const int row0 = blockIdx.x * 64;
    const int z = blockIdx.z, b = z >> 1, h = z & 1;
    const int lrow = tid >> 2, lk4 = (tid & 3) * 4;
    float acc[4][4] = {};
    for (int kt = 0; kt < 16; ++kt) {
        const int kk = kt * 16 + lk4;
        float4 av = *(const float4*)(Sc + (size_t)z*4194304 + (size_t)(row0 + lrow)*256 + kk);
        float4 wv = *(const float4*)(Vt + (size_t)z*16384 + (size_t)lrow*256 + kk);
        As[lk4+0][lrow]=av.x; As[lk4+1][lrow]=av.y; As[lk4+2][lrow]=av.z; As[lk4+3][lrow]=av.w;
        Ws[lk4+0][lrow]=wv.x; Ws[lk4+1][lrow]=wv.y; Ws[lk4+2][lrow]=wv.z; Ws[lk4+3][lrow]=wv.w;
        __syncthreads();
        #pragma unroll
        for (int k = 0; k < 16; ++k) {
            float4 a = *(const float4*)&As[k][ty*4];
            float4 w = *(const float4*)&Ws[k][tx*4];
            acc[0][0]+=a.x*w.x; acc[0][1]+=a.x*w.y; acc[0][2]+=a.x*w.z; acc[0][3]+=a.x*w.w;
            acc[1][0]+=a.y*w.x; acc[1][1]+=a.y*w.y; acc[1][2]+=a.y*w.z; acc[1][3]+=a.y*w.w;
            acc[2][0]+=a.z*w.x; acc[2][1]+=a.z*w.y; acc[2][2]+=a.z*w.z; acc[2][3]+=a.z*w.w;
            acc[3][0]+=a.w*w.x; acc[3][1]+=a.w*w.y; acc[3][2]+=a.w*w.z; acc[3][3]+=a.w*w.w;
        }
        __syncthreads();
    }
    #pragma unroll
    for (int i = 0; i < 4; ++i) {
        float4 o4 = make_float4(acc[i][0], acc[i][1], acc[i][2], acc[i][3]);
        *(float4*)(XA + (size_t)(b*NTOK + row0 + ty*4 + i)*128 + h*64 + tx*4) = o4;
    }
}

// row softmax over 128, one block per row
__global__ void softmax128_k(float* __restrict__ S)
{
    const int c = threadIdx.x;
    float* row = S + (size_t)blockIdx.x * 128;
    float v = row[c];
    __shared__ float sm[4], sm2[4];
    float m = v;
    #pragma unroll
    for (int o = 16; o; o >>= 1) m = fmaxf(m, __shfl_xor_sync(0xffffffffu, m, o));
    if ((c & 31) == 0) sm[c >> 5] = m;
    __syncthreads();
    m = fmaxf(fmaxf(sm[0],sm[1]), fmaxf(sm[2],sm[3]));
    const float e = __expf(v - m);
    float s = e;
    #pragma unroll
    for (int o = 16; o; o >>= 1) s += __shfl_xor_sync(0xffffffffu, s, o);
    if ((c & 31) == 0) sm2[c >> 5] = s;
    __syncthreads();
    s = sm2[0]+sm2[1]+sm2[2]+sm2[3];
    row[c] = e / s;
}

// constants: ck[c] = noise_k @ Wk^T row c, cv[c] = noise_v @ Wv^T row c
__global__ void cvec_k(const float* __restrict__ kn, const float* __restrict__ vn,
                       const float* __restrict__ inw, float* __restrict__ cst)
{
    const int t = threadIdx.x;  // 256
    const float* w = (t < 128) ? inw + 128*128 + (size_t)t*128
                               : inw + 256*128 + (size_t)(t-128)*128;
    const float* nz = (t < 128) ? kn : vn;
    float s = 0.f;
    #pragma unroll 8
    for (int j = 0; j < 128; ++j) s += nz[j] * w[j];
    cst[t] = s;
}

// 2-key cross attention combine: per token, per head(8,d=16)
__global__ void combine_k(const float* __restrict__ QKV, const float* __restrict__ K1,
                          const float* __restrict__ V1, const float* __restrict__ CST,
                          float* __restrict__ OB)
{
    const int n = blockIdx.x, c = threadIdx.x;  // 128 threads
    const float* qrow = QKV + (size_t)n * 384;
    const float qp  = qrow[c];
    const float kp0 = qrow[128 + c] + CST[c];
    const float kp1 = K1[(size_t)n * 128 + c];
    float s0 = qp * kp0, s1 = qp * kp1;
    #pragma unroll
    for (int o = 8; o; o >>= 1) {
        s0 += __shfl_xor_sync(0xffffffffu, s0, o, 16);
        s1 += __shfl_xor_sync(0xffffffffu, s1, o, 16);
    }
    s0 *= 0.25f; s1 *= 0.25f;
    const float m = fmaxf(s0, s1);
    const float e0 = __expf(s0 - m), e1 = __expf(s1 - m);
    const float inv = 1.0f / (e0 + e1);
    const float vp0 = qrow[256 + c] + CST[128 + c];
    const float vp1 = V1[(size_t)n * 128 + c];
    OB[(size_t)n * 128 + c] = e0 * inv * vp0 + e1 * inv * vp1;
}

extern "C" void kernel_launch(void* const* d_in, const int* in_sizes, int n_in,
                              void* d_out, int out_size)
{
    const float* x0        = (const float*)d_in[0];
    const float* x1        = (const float*)d_in[1];
    const float* Wq        = (const float*)d_in[2];
    const float* bq        = (const float*)d_in[3];
    const float* Wkv       = (const float*)d_in[4];
    const float* bkv       = (const float*)d_in[5];
    const float* sr_w      = (const float*)d_in[6];
    const float* sr_b      = (const float*)d_in[7];
    const float* ln0_g     = (const float*)d_in[8];
    const float* ln0_b     = (const float*)d_in[9];
    const float* ln1_g     = (const float*)d_in[10];
    const float* ln1_b     = (const float*)d_in[11];
    const float* ca01_in_w = (const float*)d_in[12];
    const float* ca01_in_b = (const float*)d_in[13];
    const float* ca01_out_w= (const float*)d_in[14];
    const float* ca01_out_b= (const float*)d_in[15];
    const float* ca10_in_w = (const float*)d_in[16];
    const float* ca10_in_b = (const float*)d_in[17];
    const float* ca10_out_w= (const float*)d_in[18];
    const float* ca10_out_b= (const float*)d_in[19];
    const float* rj_w1     = (const float*)d_in[20];
    const float* rj_b1     = (const float*)d_in[21];
    const float* rj_w2     = (const float*)d_in[22];
    const float* rj_b2     = (const float*)d_in[23];
    const float* k_noise   = (const float*)d_in[24];
    const float* v_noise   = (const float*)d_in[25];
    const float* proj_w    = (const float*)d_in[26];
    const float* proj_b    = (const float*)d_in[27];

    float* P = nullptr;
    cudaGetSymbolAddress((void**)&P, g_pool);
    float *XA0=P+OFF_XA0, *XA1=P+OFF_XA1, *Q=P+OFF_Q, *IM=P+OFF_IM, *PART=P+OFF_PART;
    float *WC=P+OFF_WC, *XILN=P+OFF_XILN, *KVB=P+OFF_KVB, *KH=P+OFF_KH, *VHT=P+OFF_VHT;
    float *SC=P+OFF_SC, *HB=P+OFF_H, *SB=P+OFF_S, *QKVB=P+OFF_QKV, *K1=P+OFF_K1;
    float *V1=P+OFF_V1, *OB=P+OFF_OB, *N0=P+OFF_N0, *N1=P+OFF_N1, *CST=P+OFF_CST;

    wconv_k<<<4096, 256>>>(sr_w, WC);

    // --- SR attention per stream ---
    for (int s = 0; s < 2; ++s) {
        const float* xs = s ? x1 : x0;
        const float* g  = s ? ln1_g : ln0_g;
        const float* be = s ? ln1_b : ln0_b;
        float* XA = s ? XA1 : XA0;
        gemm_k<128,8,0,0><<<dim3(1024,2), 256>>>(xs, nullptr, Wq, bq, nullptr, Q, 128, NB);
        im2col_k<<<1024, 256>>>(xs, IM);
        gemm_k<8192,32,0,3><<<dim3(16,2,16), 256>>>(IM, nullptr, WC, nullptr, nullptr, PART, 128, 1024);
        convred_ln_k<<<1024, 128>>>(PART, sr_b, g, be, XILN);
        gemm_k<128,8,0,0><<<dim3(16,4), 256>>>(XILN, nullptr, Wkv, bkv, nullptr, KVB, 256, 1024);
        kvsplit_k<<<512, 256>>>(KVB, KH, VHT);
        sr_scores_k<<<dim3(256,4,8), 256>>>(Q, KH, SC);
        softmax256_k<<<16384, 256>>>(SC);
        sr_pv_k<<<dim3(256,1,8), 256>>>(SC, VHT, XA);
    }

    // --- judger + mha2 per stream ---
    for (int s = 0; s < 2; ++s) {
        const float* A  = s ? XA1 : XA0;
        const float* Bx = s ? XA0 : XA1;
        const float* inw = s ? ca10_in_w : ca01_in_w;
        const float* inb = s ? ca10_in_b : ca01_in_b;
        const float* ow  = s ? ca10_out_w : ca01_out_w;
        const float* ob  = s ? ca10_out_b : ca01_out_b;
        float* Nbuf = s ? N1 : N0;
        gemm_k<256,16,1,1><<<dim3(1024,2), 256>>>(A, Bx, rj_w1, rj_b1, nullptr, HB, 128, NB);
        gemm_k<128,8,0,0><<<dim3(1024,2), 256>>>(HB, nullptr, rj_w2, rj_b2, nullptr, SB, 128, NB);
        softmax128_k<<<65536, 128>>>(SB);
        cvec_k<<<1, 256>>>(k_noise + s*128, v_noise + s*128, inw, CST);
        gemm_k<128,8,0,0><<<dim3(1024,6), 256>>>(A, nullptr, inw, inb, nullptr, QKVB, 384, NB);
        gemm_k<128,8,2,0><<<dim3(1024,2), 256>>>(A, SB, inw + 128*128, inb + 128, nullptr, K1, 128, NB);
        gemm_k<128,8,0,0><<<dim3(1024,2), 256>>>(Bx, nullptr, inw + 256*128, inb + 256, nullptr, V1, 128, NB);
        combine_k<<<65536, 128>>>(QKVB, K1, V1, CST, OB);
        gemm_k<128,8,0,2><<<dim3(1024,2), 256>>>(OB, nullptr, ow, ob, A, Nbuf, 128, NB);
    }

    float* out = (float*)d_out;
    gemm_k<128,8,0,0><<<dim3(1024,2), 256>>>(N0, nullptr, proj_w, proj_b, nullptr, out, 128, NB);
    gemm_k<128,8,0,0><<<dim3(1024,2), 256>>>(N1, nullptr, proj_w, proj_b, nullptr, out + SZ_TOK, 128, NB);
}

// round 4
// speedup vs baseline: 1.6851x; 1.6851x over previous
#include <cuda_runtime.h>
#include <math.h>
#include <stdint.h>
#include <stddef.h>

#define NTOK 16384
#define CD   128
#define NB   65536
#define BMR  1024
#define KCONV 8192
#define CONVZ 32

static constexpr size_t SZ_TOK  = (size_t)NB * CD;
static constexpr size_t OFF_XA0 = 0;
static constexpr size_t OFF_XA1 = OFF_XA0 + SZ_TOK;
static constexpr size_t OFF_Q   = OFF_XA1 + SZ_TOK;
static constexpr size_t OFF_IM  = OFF_Q   + SZ_TOK;
static constexpr size_t OFF_PART= OFF_IM  + SZ_TOK;
static constexpr size_t OFF_WC  = OFF_PART+ (size_t)CONVZ*BMR*CD;
static constexpr size_t OFF_XILN= OFF_WC  + (size_t)CD*KCONV;
static constexpr size_t OFF_KVB = OFF_XILN+ (size_t)BMR*CD;
static constexpr size_t OFF_KH  = OFF_KVB + (size_t)BMR*2*CD;
static constexpr size_t OFF_VHT = OFF_KH  + (size_t)8*256*64;
static constexpr size_t OFF_SC  = OFF_VHT + (size_t)8*256*64;
static constexpr size_t OFF_H   = OFF_SC  + (size_t)8*NTOK*256;
static constexpr size_t OFF_S   = OFF_H   + SZ_TOK;
static constexpr size_t OFF_QKV = OFF_S   + SZ_TOK;
static constexpr size_t OFF_K1  = OFF_QKV + (size_t)NB*384;
static constexpr size_t OFF_V1  = OFF_K1  + SZ_TOK;
static constexpr size_t OFF_OB  = OFF_V1  + SZ_TOK;
static constexpr size_t OFF_N0  = OFF_OB  + SZ_TOK;
static constexpr size_t OFF_N1  = OFF_N0  + SZ_TOK;
static constexpr size_t OFF_CST = OFF_N1  + SZ_TOK;
static constexpr size_t POOL_SZ = OFF_CST + 256;

__device__ float g_pool[POOL_SZ];

__device__ __forceinline__ float geluf(float x) {
    return 0.5f * x * (1.0f + erff(x * 0.70710678118654752f));
}
__device__ __forceinline__ uint32_t f2tf32(float x) {
    uint32_t r; asm("cvt.rna.tf32.f32 %0, %1;" : "=r"(r) : "f"(x)); return r;
}
__device__ __forceinline__ void mma8(float* c, const uint32_t* a, const uint32_t* b) {
    asm volatile("mma.sync.aligned.m16n8k8.row.col.f32.tf32.tf32.f32 "
        "{%0,%1,%2,%3}, {%4,%5,%6,%7}, {%8,%9}, {%0,%1,%2,%3};"
        : "+f"(c[0]), "+f"(c[1]), "+f"(c[2]), "+f"(c[3])
        : "r"(a[0]), "r"(a[1]), "r"(a[2]), "r"(a[3]), "r"(b[0]), "r"(b[1]));
}

// ---------------------------------------------------------------------------
// tf32 tensor GEMM: out[.. x ncols] = A @ W^T (+bias/epilogue).
// Tile 128 x BN, BK=32, 256 threads (8 warps), m16n8k8 tf32 MMA.
// AMODE: 0 plain; 1 K-concat(A0,A1); 2 elementwise A0*A1;
//        3 SR scores (z batched: A=Q(b,h), W=Kh[z], out=Sc[z]);
//        4 SR PV     (z batched: A=Sc[z], W=Vt[z], out=XA(b,h)).
// EPI: 0 +bias; 1 +bias,gelu; 2 +bias,+res; 3 raw K-split partial; 4 raw.
// ---------------------------------------------------------------------------
template<int KTILES, int BN, int AMODE, int EPI>
__global__ void __launch_bounds__(256, 2) tgemm_k(
    const float* __restrict__ A0, const float* __restrict__ A1,
    const float* __restrict__ W,  const float* __restrict__ bias,
    const float* __restrict__ res, float* __restrict__ out,
    int lda, int ldw, int ldo)
{
    constexpr int PADA = 136;
    constexpr int PADB = BN + 8;
    constexpr int colWarps = BN / 32;
    constexpr int rowWarps = 8 / colWarps;
    constexpr int WM = 128 / rowWarps;
    constexpr int MT = WM / 16;
    constexpr int WF4 = BN / 32;           // float4 W loads per thread

    __shared__ uint32_t As[32 * PADA];
    __shared__ uint32_t Ws[32 * PADB];

    const int tid = threadIdx.x;
    const int w = tid >> 5, lane = tid & 31, g = lane >> 2, t = lane & 3;
    const int warpRow = w / colWarps, warpCol = w % colWarps;
    const int row0 = blockIdx.x * 128, col0 = blockIdx.y * BN;
    const int z = blockIdx.z;

    const float* Ap = A0;
    const float* Wp = W;
    float* op = out;
    if (AMODE == 3) {
        Ap = A0 + ((size_t)(z >> 1) * NTOK * 128 + (z & 1) * 64);
        Wp = W + (size_t)z * 16384;
        op = out + (size_t)z * NTOK * 256;
    } else if (AMODE == 4) {
        Ap = A0 + (size_t)z * NTOK * 256;
        Wp = W + (size_t)z * 16384;
        op = out + ((size_t)(z >> 1) * NTOK * 128 + (z & 1) * 64);
    }
    if (EPI == 3) op = out + (size_t)z * (BMR * CD);
    const int koff0 = (EPI == 3) ? z * KTILES * 32 : 0;

    float acc[MT][4][4] = {};

    for (int kt = 0; kt < KTILES; ++kt) {
        const int koff = koff0 + kt * 32;
        // load A tile (128 x 32) -> As[k][m], tf32
        #pragma unroll
        for (int i = 0; i < 4; ++i) {
            const int fidx = i * 256 + tid;
            const int arow = fidx >> 3, kq = (fidx & 7) * 4;
            const int kg = koff + kq;
            float4 v;
            if (AMODE == 1) {
                const float* src = (kg < 128)
                    ? (A0 + (size_t)(row0 + arow) * 128 + kg)
                    : (A1 + (size_t)(row0 + arow) * 128 + (kg - 128));
                v = *(const float4*)src;
            } else if (AMODE == 2) {
                float4 a = *(const float4*)(A0 + (size_t)(row0 + arow) * lda + kg);
                float4 b = *(const float4*)(A1 + (size_t)(row0 + arow) * lda + kg);
                v = make_float4(a.x*b.x, a.y*b.y, a.z*b.z, a.w*b.w);
            } else {
                v = *(const float4*)(Ap + (size_t)(row0 + arow) * lda + kg);
            }
            As[(kq+0)*PADA + arow] = f2tf32(v.x);
            As[(kq+1)*PADA + arow] = f2tf32(v.y);
            As[(kq+2)*PADA + arow] = f2tf32(v.z);
            As[(kq+3)*PADA + arow] = f2tf32(v.w);
        }
        // load W tile (BN x 32) -> Ws[k][n], tf32
        #pragma unroll
        for (int i = 0; i < WF4; ++i) {
            const int fidx = i * 256 + tid;
            const int wrow = fidx >> 3, kq = (fidx & 7) * 4;
            float4 v = *(const float4*)(Wp + (size_t)(col0 + wrow) * ldw + koff + kq);
            Ws[(kq+0)*PADB + wrow] = f2tf32(v.x);
            Ws[(kq+1)*PADB + wrow] = f2tf32(v.y);
            Ws[(kq+2)*PADB + wrow] = f2tf32(v.z);
            Ws[(kq+3)*PADB + wrow] = f2tf32(v.w);
        }
        __syncthreads();

        #pragma unroll
        for (int k0 = 0; k0 < 32; k0 += 8) {
            uint32_t bf[4][2];
            #pragma unroll
            for (int nt = 0; nt < 4; ++nt) {
                const int nb = warpCol * 32 + nt * 8 + g;
                bf[nt][0] = Ws[(k0 + t)     * PADB + nb];
                bf[nt][1] = Ws[(k0 + t + 4) * PADB + nb];
            }
            #pragma unroll
            for (int mt = 0; mt < MT; ++mt) {
                const int rb = warpRow * WM + mt * 16 + g;
                uint32_t af[4];
                af[0] = As[(k0 + t)     * PADA + rb];
                af[1] = As[(k0 + t)     * PADA + rb + 8];
                af[2] = As[(k0 + t + 4) * PADA + rb];
                af[3] = As[(k0 + t + 4) * PADA + rb + 8];
                #pragma unroll
                for (int nt = 0; nt < 4; ++nt) mma8(acc[mt][nt], af, bf[nt]);
            }
        }
        __syncthreads();
    }

    // epilogue
    #pragma unroll
    for (int mt = 0; mt < MT; ++mt) {
        const int r = row0 + warpRow * WM + mt * 16 + g;
        #pragma unroll
        for (int nt = 0; nt < 4; ++nt) {
            const int cc = col0 + warpCol * 32 + nt * 8 + 2 * t;
            float v0 = acc[mt][nt][0], v1 = acc[mt][nt][1];
            float v2 = acc[mt][nt][2], v3 = acc[mt][nt][3];
            if (EPI == 0 || EPI == 1 || EPI == 2) {
                const float bx = bias[cc], by = bias[cc + 1];
                v0 += bx; v1 += by; v2 += bx; v3 += by;
            }
            if (EPI == 1) { v0=geluf(v0); v1=geluf(v1); v2=geluf(v2); v3=geluf(v3); }
            if (EPI == 2) {
                float2 r0 = *(const float2*)(res + (size_t)r * ldo + cc);
                float2 r1 = *(const float2*)(res + (size_t)(r + 8) * ldo + cc);
                v0 += r0.x; v1 += r0.y; v2 += r1.x; v3 += r1.y;
            }
            *(float2*)(op + (size_t)r       * ldo + cc) = make_float2(v0, v1);
            *(float2*)(op + (size_t)(r + 8) * ldo + cc) = make_float2(v2, v3);
        }
    }
}

// im2col: row (b,ph,pw) -> K = (i*8+j)*128 + c
__global__ void im2col_k(const float* __restrict__ x, float* __restrict__ im)
{
    const int row = blockIdx.x;
    const int b = row >> 8, p = row & 255, ph = p >> 4, pw = p & 15;
    const float* xb = x + (size_t)b * NTOK * CD;
    float* dst = im + (size_t)row * KCONV;
    for (int k = threadIdx.x; k < KCONV; k += blockDim.x) {
        const int ij = k >> 7, c = k & 127, i = ij >> 3, j = ij & 7;
        dst[k] = xb[(size_t)((ph*8+i)*128 + pw*8+j) * CD + c];
    }
}

__global__ void wconv_k(const float* __restrict__ w, float* __restrict__ wc)
{
    const int idx = blockIdx.x * blockDim.x + threadIdx.x;
    if (idx >= CD * KCONV) return;
    const int o = idx >> 13, k = idx & 8191, ij = k >> 7, c = k & 127;
    wc[idx] = w[(size_t)o * 8192 + c * 64 + ij];
}

__global__ void convred_ln_k(const float* __restrict__ part, const float* __restrict__ sb,
                             const float* __restrict__ g, const float* __restrict__ be,
                             float* __restrict__ outp)
{
    const int row = blockIdx.x, c = threadIdx.x;
    float v = sb[c];
    #pragma unroll
    for (int z = 0; z < CONVZ; ++z)
        v += part[(size_t)z * BMR * CD + (size_t)row * CD + c];
    __shared__ float red[4], red2[4];
    float s = v;
    #pragma unroll
    for (int o = 16; o; o >>= 1) s += __shfl_xor_sync(0xffffffffu, s, o);
    if ((c & 31) == 0) red[c >> 5] = s;
    __syncthreads();
    const float mean = (red[0]+red[1]+red[2]+red[3]) * (1.0f/CD);
    const float d = v - mean;
    float s2 = d * d;
    #pragma unroll
    for (int o = 16; o; o >>= 1) s2 += __shfl_xor_sync(0xffffffffu, s2, o);
    if ((c & 31) == 0) red2[c >> 5] = s2;
    __syncthreads();
    const float var = (red2[0]+red2[1]+red2[2]+red2[3]) * (1.0f/CD);
    outp[(size_t)row * CD + c] = d * rsqrtf(var + 1e-5f) * g[c] + be[c];
}

// split KV into per-(b,h) K [z][m][d] (pre-scaled by 1/8) and V^T [z][d][m]
__global__ void kvsplit_k(const float* __restrict__ KVb, float* __restrict__ Kh,
                          float* __restrict__ Vt)
{
    const int idx = blockIdx.x * blockDim.x + threadIdx.x;
    if (idx >= 8*256*64) return;
    const int z = idx >> 14, r = idx & 16383, m = r >> 6, d = r & 63;
    const int b = z >> 1, h = z & 1;
    const float* src = KVb + (size_t)(b*256 + m) * 256 + h*64 + d;
    Kh[idx] = src[0] * 0.125f;
    Vt[(size_t)z*16384 + d*256 + m] = src[128];
}

__global__ void softmax256_k(float* __restrict__ S)
{
    const int row = blockIdx.x * 8 + (threadIdx.x >> 5);
    const int lane = threadIdx.x & 31;
    float4* p = (float4*)(S + (size_t)row * 256 + lane * 8);
    float4 a = p[0], b = p[1];
    float mx = fmaxf(fmaxf(fmaxf(a.x,a.y),fmaxf(a.z,a.w)),
                     fmaxf(fmaxf(b.x,b.y),fmaxf(b.z,b.w)));
    #pragma unroll
    for (int o = 16; o; o >>= 1) mx = fmaxf(mx, __shfl_xor_sync(0xffffffffu, mx, o));
    a.x=__expf(a.x-mx); a.y=__expf(a.y-mx); a.z=__expf(a.z-mx); a.w=__expf(a.w-mx);
    b.x=__expf(b.x-mx); b.y=__expf(b.y-mx); b.z=__expf(b.z-mx); b.w=__expf(b.w-mx);
    float s = a.x+a.y+a.z+a.w+b.x+b.y+b.z+b.w;
    #pragma unroll
    for (int o = 16; o; o >>= 1) s += __shfl_xor_sync(0xffffffffu, s, o);
    const float inv = 1.0f / s;
    a.x*=inv; a.y*=inv; a.z*=inv; a.w*=inv; b.x*=inv; b.y*=inv; b.z*=inv; b.w*=inv;
    p[0] = a; p[1] = b;
}

__global__ void softmax128_k(float* __restrict__ S)
{
    const int c = threadIdx.x;
    float* row = S + (size_t)blockIdx.x * 128;
    float v = row[c];
    __shared__ float sm[4], sm2[4];
    float m = v;
    #pragma unroll
    for (int o = 16; o; o >>= 1) m = fmaxf(m, __shfl_xor_sync(0xffffffffu, m, o));
    if ((c & 31) == 0) sm[c >> 5] = m;
    __syncthreads();
    m = fmaxf(fmaxf(sm[0],sm[1]), fmaxf(sm[2],sm[3]));
    const float e = __expf(v - m);
    float s = e;
    #pragma unroll
    for (int o = 16; o; o >>= 1) s += __shfl_xor_sync(0xffffffffu, s, o);
    if ((c & 31) == 0) sm2[c >> 5] = s;
    __syncthreads();
    s = sm2[0]+sm2[1]+sm2[2]+sm2[3];
    row[c] = e / s;
}

__global__ void cvec_k(const float* __restrict__ kn, const float* __restrict__ vn,
                       const float* __restrict__ inw, float* __restrict__ cst)
{
    const int t = threadIdx.x;
    const float* w = (t < 128) ? inw + 128*128 + (size_t)t*128
                               : inw + 256*128 + (size_t)(t-128)*128;
    const float* nz = (t < 128) ? kn : vn;
    float s = 0.f;
    #pragma unroll 8
    for (int j = 0; j < 128; ++j) s += nz[j] * w[j];
    cst[t] = s;
}

__global__ void combine_k(const float* __restrict__ QKV, const float* __restrict__ K1,
                          const float* __restrict__ V1, const float* __restrict__ CST,
                          float* __restrict__ OB)
{
    const int n = blockIdx.x, c = threadIdx.x;
    const float* qrow = QKV + (size_t)n * 384;
    const float qp  = qrow[c];
    const float kp0 = qrow[128 + c] + CST[c];
    const float kp1 = K1[(size_t)n * 128 + c];
    float s0 = qp * kp0, s1 = qp * kp1;
    #pragma unroll
    for (int o = 8; o; o >>= 1) {
        s0 += __shfl_xor_sync(0xffffffffu, s0, o, 16);
        s1 += __shfl_xor_sync(0xffffffffu, s1, o, 16);
    }
    s0 *= 0.25f; s1 *= 0.25f;
    const float m = fmaxf(s0, s1);
    const float e0 = __expf(s0 - m), e1 = __expf(s1 - m);
    const float inv = 1.0f / (e0 + e1);
    const float vp0 = qrow[256 + c] + CST[128 + c];
    const float vp1 = V1[(size_t)n * 128 + c];
    OB[(size_t)n * 128 + c] = e0 * inv * vp0 + e1 * inv * vp1;
}

extern "C" void kernel_launch(void* const* d_in, const int* in_sizes, int n_in,
                              void* d_out, int out_size)
{
    const float* x0        = (const float*)d_in[0];
    const float* x1        = (const float*)d_in[1];
    const float* Wq        = (const float*)d_in[2];
    const float* bq        = (const float*)d_in[3];
    const float* Wkv       = (const float*)d_in[4];
    const float* bkv       = (const float*)d_in[5];
    const float* sr_w      = (const float*)d_in[6];
    const float* sr_b      = (const float*)d_in[7];
    const float* ln0_g     = (const float*)d_in[8];
    const float* ln0_b     = (const float*)d_in[9];
    const float* ln1_g     = (const float*)d_in[10];
    const float* ln1_b     = (const float*)d_in[11];
    const float* ca01_in_w = (const float*)d_in[12];
    const float* ca01_in_b = (const float*)d_in[13];
    const float* ca01_out_w= (const float*)d_in[14];
    const float* ca01_out_b= (const float*)d_in[15];
    const float* ca10_in_w = (const float*)d_in[16];
    const float* ca10_in_b = (const float*)d_in[17];
    const float* ca10_out_w= (const float*)d_in[18];
    const float* ca10_out_b= (const float*)d_in[19];
    const float* rj_w1     = (const float*)d_in[20];
    const float* rj_b1     = (const float*)d_in[21];
    const float* rj_w2     = (const float*)d_in[22];
    const float* rj_b2     = (const float*)d_in[23];
    const float* k_noise   = (const float*)d_in[24];
    const float* v_noise   = (const float*)d_in[25];
    const float* proj_w    = (const float*)d_in[26];
    const float* proj_b    = (const float*)d_in[27];

    float* P = nullptr;
    cudaGetSymbolAddress((void**)&P, g_pool);
    float *XA0=P+OFF_XA0, *XA1=P+OFF_XA1, *Q=P+OFF_Q, *IM=P+OFF_IM, *PART=P+OFF_PART;
    float *WC=P+OFF_WC, *XILN=P+OFF_XILN, *KVB=P+OFF_KVB, *KH=P+OFF_KH, *VHT=P+OFF_VHT;
    float *SC=P+OFF_SC, *HB=P+OFF_H, *SB=P+OFF_S, *QKVB=P+OFF_QKV, *K1=P+OFF_K1;
    float *V1=P+OFF_V1, *OB=P+OFF_OB, *N0=P+OFF_N0, *N1=P+OFF_N1, *CST=P+OFF_CST;

    wconv_k<<<4096, 256>>>(sr_w, WC);

    // --- SR attention per stream ---
    for (int s = 0; s < 2; ++s) {
        const float* xs = s ? x1 : x0;
        const float* g  = s ? ln1_g : ln0_g;
        const float* be = s ? ln1_b : ln0_b;
        float* XA = s ? XA1 : XA0;
        tgemm_k<4,128,0,0><<<dim3(512,1), 256>>>(xs, nullptr, Wq, bq, nullptr, Q, 128, 128, 128);
        im2col_k<<<1024, 256>>>(xs, IM);
        tgemm_k<8,128,0,3><<<dim3(8,1,CONVZ), 256>>>(IM, nullptr, WC, nullptr, nullptr, PART, 8192, 8192, 128);
        convred_ln_k<<<1024, 128>>>(PART, sr_b, g, be, XILN);
        tgemm_k<4,128,0,0><<<dim3(8,2), 256>>>(XILN, nullptr, Wkv, bkv, nullptr, KVB, 128, 128, 256);
        kvsplit_k<<<512, 256>>>(KVB, KH, VHT);
        tgemm_k<2,128,3,4><<<dim3(128,2,8), 256>>>(Q, nullptr, KH, nullptr, nullptr, SC, 128, 64, 256);
        softmax256_k<<<16384, 256>>>(SC);
        tgemm_k<8,64,4,4><<<dim3(128,1,8), 256>>>(SC, nullptr, VHT, nullptr, nullptr, XA, 256, 256, 128);
    }

    // --- judger + mha2 per stream ---
    for (int s = 0; s < 2; ++s) {
        const float* A  = s ? XA1 : XA0;
        const float* Bx = s ? XA0 : XA1;
        const float* inw = s ? ca10_in_w : ca01_in_w;
        const float* inb = s ? ca10_in_b : ca01_in_b;
        const float* ow  = s ? ca10_out_w : ca01_out_w;
        const float* ob  = s ? ca10_out_b : ca01_out_b;
        float* Nbuf = s ? N1 : N0;
        tgemm_k<8,128,1,1><<<dim3(512,1), 256>>>(A, Bx, rj_w1, rj_b1, nullptr, HB, 128, 256, 128);
        tgemm_k<4,128,0,0><<<dim3(512,1), 256>>>(HB, nullptr, rj_w2, rj_b2, nullptr, SB, 128, 128, 128);
        softmax128_k<<<65536, 128>>>(SB);
        cvec_k<<<1, 256>>>(k_noise + s*128, v_noise + s*128, inw, CST);
        tgemm_k<4,128,0,0><<<dim3(512,3), 256>>>(A, nullptr, inw, inb, nullptr, QKVB, 128, 128, 384);
        tgemm_k<4,128,2,0><<<dim3(512,1), 256>>>(A, SB, inw + 128*128, inb + 128, nullptr, K1, 128, 128, 128);
        tgemm_k<4,128,0,0><<<dim3(512,1), 256>>>(Bx, nullptr, inw + 256*128, inb + 256, nullptr, V1, 128, 128, 128);
        combine_k<<<65536, 128>>>(QKVB, K1, V1, CST, OB);
        tgemm_k<4,128,0,2><<<dim3(512,1), 256>>>(OB, nullptr, ow, ob, A, Nbuf, 128, 128, 128);
    }

    float* out = (float*)d_out;
    tgemm_k<4,128,0,0><<<dim3(512,1), 256>>>(N0, nullptr, proj_w, proj_b, nullptr, out, 128, 128, 128);
    tgemm_k<4,128,0,0><<<dim3(512,1), 256>>>(N1, nullptr, proj_w, proj_b, nullptr, out + SZ_TOK, 128, 128, 128);
}

// round 5
// speedup vs baseline: 2.3710x; 1.4070x over previous
#include <cuda_runtime.h>
#include <math.h>
#include <stdint.h>
#include <stddef.h>

#define NTOK 16384
#define CD   128
#define NB   65536
#define BMR  1024
#define KCONV 8192

static constexpr size_t SZ = (size_t)NB * CD;   // 8388608
static constexpr size_t OFF_XA0 = 0;
static constexpr size_t OFF_XA1 = SZ;
static constexpr size_t OFF_Q   = 2*SZ;          // 2 slices
static constexpr size_t OFF_IM  = 4*SZ;          // 2 slices
static constexpr size_t OFF_PART= 6*SZ;          // 64*1024*128 = SZ
static constexpr size_t OFF_WC  = 7*SZ;
static constexpr size_t OFF_XILN= OFF_WC  + (size_t)CD*KCONV;
static constexpr size_t OFF_KVB = OFF_XILN+ (size_t)2*BMR*CD;
static constexpr size_t OFF_KH  = OFF_KVB + (size_t)2*BMR*2*CD;
static constexpr size_t OFF_VHT = OFF_KH  + (size_t)16*256*64;
static constexpr size_t OFF_SC  = OFF_VHT + (size_t)16*256*64;
static constexpr size_t OFF_HB  = OFF_SC  + (size_t)16*NTOK*256;
static constexpr size_t OFF_SB  = OFF_HB  + 2*SZ;
static constexpr size_t OFF_QKV = OFF_SB  + 2*SZ;
static constexpr size_t OFF_K1  = OFF_QKV + (size_t)NB*384;
static constexpr size_t OFF_V1  = OFF_K1  + SZ;
static constexpr size_t OFF_OB  = OFF_V1  + SZ;
static constexpr size_t OFF_N0  = OFF_OB  + SZ;
static constexpr size_t OFF_N1  = OFF_N0  + SZ;
static constexpr size_t OFF_CST = OFF_N1  + SZ;
static constexpr size_t POOL_SZ = OFF_CST + 256;

__device__ float g_pool[POOL_SZ];

__device__ __forceinline__ float geluf(float x) {
    return 0.5f * x * (1.0f + erff(x * 0.70710678118654752f));
}
__device__ __forceinline__ uint32_t f2tf32(float x) {
    uint32_t r; asm("cvt.rna.tf32.f32 %0, %1;" : "=r"(r) : "f"(x)); return r;
}
__device__ __forceinline__ void mma8(float* c, const uint32_t* a, const uint32_t* b) {
    asm volatile("mma.sync.aligned.m16n8k8.row.col.f32.tf32.tf32.f32 "
        "{%0,%1,%2,%3}, {%4,%5,%6,%7}, {%8,%9}, {%0,%1,%2,%3};"
        : "+f"(c[0]), "+f"(c[1]), "+f"(c[2]), "+f"(c[3])
        : "r"(a[0]), "r"(a[1]), "r"(a[2]), "r"(a[3]), "r"(b[0]), "r"(b[1]));
}
__device__ __forceinline__ void ldsm4(uint32_t* r, uint32_t addr) {
    asm volatile("ldmatrix.sync.aligned.m8n8.x4.shared.b16 {%0,%1,%2,%3}, [%4];"
        : "=r"(r[0]), "=r"(r[1]), "=r"(r[2]), "=r"(r[3]) : "r"(addr));
}
__device__ __forceinline__ void ldsm2(uint32_t* r, uint32_t addr) {
    asm volatile("ldmatrix.sync.aligned.m8n8.x2.shared.b16 {%0,%1}, [%2];"
        : "=r"(r[0]), "=r"(r[1]) : "r"(addr));
}

// ---------------------------------------------------------------------------
// tf32 tensor GEMM, tile 128 x BN, BK=32, 8 warps, ldmatrix fragment loads.
// AMODE: 0 plain (z-batched via zsa/zso); 1 K-concat(A0,A1); 2 A0*A1;
//        3 SR scores (z=st*8+b*2+h); 4 SR PV; 6 concat-swap by z; 7 conv z=64.
// EPI:   0 +bias; 1 +bias,gelu; 2 +bias,+res; 4 raw.
// ---------------------------------------------------------------------------
template<int KTILES, int BN, int AMODE, int EPI>
__global__ void __launch_bounds__(256, 2) tgemm_k(
    const float* __restrict__ A0, const float* __restrict__ A1,
    const float* __restrict__ W,  const float* __restrict__ bias,
    const float* __restrict__ res, float* __restrict__ out,
    int lda, int ldw, int ldo, size_t zsa, size_t zso)
{
    constexpr int PAD = 36;                  // floats per smem row (9 x 16B)
    constexpr int colWarps = BN / 32;
    constexpr int rowWarps = 8 / colWarps;
    constexpr int WM = 128 / rowWarps;
    constexpr int MT = WM / 16;
    constexpr int WF4 = BN / 32;

    __shared__ uint32_t As[128 * PAD];
    __shared__ uint32_t Ws[BN * PAD];

    const int tid = threadIdx.x;
    const int w = tid >> 5, lane = tid & 31, g = lane >> 2, t = lane & 3;
    const int warpRow = w / colWarps, warpCol = w % colWarps;
    const int row0 = blockIdx.x * 128, col0 = blockIdx.y * BN;
    const int z = blockIdx.z;

    const float* Ap = A0 + z * zsa;
    const float* Aa = A0; const float* Ab = A1;
    const float* Wp = W;
    float* op = out + z * zso;
    int koff0 = 0;
    if (AMODE == 3) {
        Ap = A0 + (size_t)(z >> 3) * SZ + (size_t)((z >> 1) & 3) * (NTOK * 128) + (z & 1) * 64;
        Wp = W + (size_t)z * 16384;
        op = out + (size_t)z * NTOK * 256;
    } else if (AMODE == 4) {
        Ap = A0 + (size_t)z * NTOK * 256;
        Wp = W + (size_t)z * 16384;
        op = out + (size_t)(z >> 3) * SZ + (size_t)((z >> 1) & 3) * (NTOK * 128) + (z & 1) * 64;
    } else if (AMODE == 6) {
        Aa = z ? A1 : A0; Ab = z ? A0 : A1;
    } else if (AMODE == 7) {
        Ap = A0 + (size_t)(z >> 5) * ((size_t)BMR * KCONV);
        koff0 = (z & 31) * (KTILES * 32);
        op = out + (size_t)z * (BMR * CD);
    }

    // per-lane ldmatrix address components
    const int laneRowA = ((lane >> 3) & 1) * 8 + (lane & 7);
    const int laneKA   = (lane >> 4) * 4;
    const int laneRowB = lane & 7;
    const int laneKB   = ((lane >> 3) & 1) * 4;
    const uint32_t aBase = (uint32_t)__cvta_generic_to_shared(As);
    const uint32_t wBase = (uint32_t)__cvta_generic_to_shared(Ws);

    float acc[MT][4][4] = {};

    for (int kt = 0; kt < KTILES; ++kt) {
        const int koff = koff0 + kt * 32;
        #pragma unroll
        for (int i = 0; i < 4; ++i) {
            const int fidx = i * 256 + tid;
            const int arow = fidx >> 3, kq = (fidx & 7) * 4;
            const int kg = koff + kq;
            float4 v;
            if (AMODE == 1 || AMODE == 6) {
                const float* src = (kg < 128)
                    ? (Aa + (size_t)(row0 + arow) * 128 + kg)
                    : (Ab + (size_t)(row0 + arow) * 128 + (kg - 128));
                v = *(const float4*)src;
            } else if (AMODE == 2) {
                float4 a = *(const float4*)(A0 + (size_t)(row0 + arow) * lda + kg);
                float4 b = *(const float4*)(A1 + (size_t)(row0 + arow) * lda + kg);
                v = make_float4(a.x*b.x, a.y*b.y, a.z*b.z, a.w*b.w);
            } else {
                v = *(const float4*)(Ap + (size_t)(row0 + arow) * lda + kg);
            }
            uint4 u = make_uint4(f2tf32(v.x), f2tf32(v.y), f2tf32(v.z), f2tf32(v.w));
            *(uint4*)&As[arow * PAD + kq] = u;
        }
        #pragma unroll
        for (int i = 0; i < WF4; ++i) {
            const int fidx = i * 256 + tid;
            const int wrow = fidx >> 3, kq = (fidx & 7) * 4;
            float4 v = *(const float4*)(Wp + (size_t)(col0 + wrow) * ldw + koff + kq);
            uint4 u = make_uint4(f2tf32(v.x), f2tf32(v.y), f2tf32(v.z), f2tf32(v.w));
            *(uint4*)&Ws[wrow * PAD + kq] = u;
        }
        __syncthreads();

        #pragma unroll
        for (int k0 = 0; k0 < 32; k0 += 8) {
            uint32_t bf[4][2];
            #pragma unroll
            for (int nt = 0; nt < 4; ++nt) {
                const uint32_t addr = wBase + 4u * ((warpCol*32 + nt*8 + laneRowB) * PAD + laneKB + k0);
                ldsm2(bf[nt], addr);
            }
            #pragma unroll
            for (int mt = 0; mt < MT; ++mt) {
                uint32_t af[4];
                const uint32_t addr = aBase + 4u * ((warpRow*WM + mt*16 + laneRowA) * PAD + laneKA + k0);
                ldsm4(af, addr);
                #pragma unroll
                for (int nt = 0; nt < 4; ++nt) mma8(acc[mt][nt], af, bf[nt]);
            }
        }
        __syncthreads();
    }

    #pragma unroll
    for (int mt = 0; mt < MT; ++mt) {
        const int r = row0 + warpRow * WM + mt * 16 + g;
        #pragma unroll
        for (int nt = 0; nt < 4; ++nt) {
            const int cc = col0 + warpCol * 32 + nt * 8 + 2 * t;
            float v0 = acc[mt][nt][0], v1 = acc[mt][nt][1];
            float v2 = acc[mt][nt][2], v3 = acc[mt][nt][3];
            if (EPI == 0 || EPI == 1 || EPI == 2) {
                const float bx = bias[cc], by = bias[cc + 1];
                v0 += bx; v1 += by; v2 += bx; v3 += by;
            }
            if (EPI == 1) { v0=geluf(v0); v1=geluf(v1); v2=geluf(v2); v3=geluf(v3); }
            if (EPI == 2) {
                float2 r0 = *(const float2*)(res + (size_t)r * ldo + cc);
                float2 r1 = *(const float2*)(res + (size_t)(r + 8) * ldo + cc);
                v0 += r0.x; v1 += r0.y; v2 += r1.x; v3 += r1.y;
            }
            *(float2*)(op + (size_t)r       * ldo + cc) = make_float2(v0, v1);
            *(float2*)(op + (size_t)(r + 8) * ldo + cc) = make_float2(v2, v3);
        }
    }
}

// im2col both streams: row (s,b,ph,pw) -> K = (i*8+j)*128 + c
__global__ void im2col_k(const float* __restrict__ x0, const float* __restrict__ x1,
                         float* __restrict__ im)
{
    const int row = blockIdx.x;                 // 0..2047
    const int s = row >> 10, rl = row & 1023;
    const int b = rl >> 8, p = rl & 255, ph = p >> 4, pw = p & 15;
    const float* xb = (s ? x1 : x0) + (size_t)b * NTOK * CD;
    float* dst = im + (size_t)row * KCONV;
    for (int k = threadIdx.x; k < KCONV; k += blockDim.x) {
        const int ij = k >> 7, c = k & 127, i = ij >> 3, j = ij & 7;
        dst[k] = xb[(size_t)((ph*8+i)*128 + pw*8+j) * CD + c];
    }
}

__global__ void wconv_k(const float* __restrict__ w, float* __restrict__ wc)
{
    const int idx = blockIdx.x * blockDim.x + threadIdx.x;
    if (idx >= CD * KCONV) return;
    const int o = idx >> 13, k = idx & 8191, ij = k >> 7, c = k & 127;
    wc[idx] = w[(size_t)o * 8192 + c * 64 + ij];
}

// reduce conv K-partials (32 per stream) + bias + layernorm, both streams
__global__ void convred_ln_k(const float* __restrict__ part, const float* __restrict__ sb,
                             const float* __restrict__ g0, const float* __restrict__ b0,
                             const float* __restrict__ g1, const float* __restrict__ b1,
                             float* __restrict__ outp)
{
    const int row = blockIdx.x, c = threadIdx.x;       // 2048 rows x 128
    const int s = row >> 10, rl = row & 1023;
    const float* g  = s ? g1 : g0;
    const float* be = s ? b1 : b0;
    float v = sb[c];
    #pragma unroll
    for (int zz = 0; zz < 32; ++zz)
        v += part[(size_t)(s*32 + zz) * BMR * CD + (size_t)rl * CD + c];
    __shared__ float red[4], red2[4];
    float sum = v;
    #pragma unroll
    for (int o = 16; o; o >>= 1) sum += __shfl_xor_sync(0xffffffffu, sum, o);
    if ((c & 31) == 0) red[c >> 5] = sum;
    __syncthreads();
    const float mean = (red[0]+red[1]+red[2]+red[3]) * (1.0f/CD);
    const float d = v - mean;
    float s2 = d * d;
    #pragma unroll
    for (int o = 16; o; o >>= 1) s2 += __shfl_xor_sync(0xffffffffu, s2, o);
    if ((c & 31) == 0) red2[c >> 5] = s2;
    __syncthreads();
    const float var = (red2[0]+red2[1]+red2[2]+red2[3]) * (1.0f/CD);
    outp[(size_t)row * CD + c] = d * rsqrtf(var + 1e-5f) * g[c] + be[c];
}

// split KV into per-(s,b,h) K [zz][m][d] (pre-scaled 1/8) and V^T [zz][d][m]
__global__ void kvsplit_k(const float* __restrict__ KVb, float* __restrict__ Kh,
                          float* __restrict__ Vt)
{
    const int idx = blockIdx.x * blockDim.x + threadIdx.x;
    if (idx >= 16*256*64) return;
    const int zz = idx >> 14, r = idx & 16383, m = r >> 6, d = r & 63;
    const int s = zz >> 3, b = (zz >> 1) & 3, h = zz & 1;
    const float* src = KVb + ((size_t)(s*1024 + b*256 + m)) * 256 + h*64 + d;
    Kh[idx] = src[0] * 0.125f;
    Vt[(size_t)zz*16384 + d*256 + m] = src[128];
}

__global__ void softmax256_k(float* __restrict__ S)
{
    const int row = blockIdx.x * 8 + (threadIdx.x >> 5);
    const int lane = threadIdx.x & 31;
    float4* p = (float4*)(S + (size_t)row * 256 + lane * 8);
    float4 a = p[0], b = p[1];
    float mx = fmaxf(fmaxf(fmaxf(a.x,a.y),fmaxf(a.z,a.w)),
                     fmaxf(fmaxf(b.x,b.y),fmaxf(b.z,b.w)));
    #pragma unroll
    for (int o = 16; o; o >>= 1) mx = fmaxf(mx, __shfl_xor_sync(0xffffffffu, mx, o));
    a.x=__expf(a.x-mx); a.y=__expf(a.y-mx); a.z=__expf(a.z-mx); a.w=__expf(a.w-mx);
    b.x=__expf(b.x-mx); b.y=__expf(b.y-mx); b.z=__expf(b.z-mx); b.w=__expf(b.w-mx);
    float s = a.x+a.y+a.z+a.w+b.x+b.y+b.z+b.w;
    #pragma unroll
    for (int o = 16; o; o >>= 1) s += __shfl_xor_sync(0xffffffffu, s, o);
    const float inv = 1.0f / s;
    a.x*=inv; a.y*=inv; a.z*=inv; a.w*=inv; b.x*=inv; b.y*=inv; b.z*=inv; b.w*=inv;
    p[0] = a; p[1] = b;
}

__global__ void softmax128_k(float* __restrict__ S)
{
    const int c = threadIdx.x;
    float* row = S + (size_t)blockIdx.x * 128;
    float v = row[c];
    __shared__ float sm[4], sm2[4];
    float m = v;
    #pragma unroll
    for (int o = 16; o; o >>= 1) m = fmaxf(m, __shfl_xor_sync(0xffffffffu, m, o));
    if ((c & 31) == 0) sm[c >> 5] = m;
    __syncthreads();
    m = fmaxf(fmaxf(sm[0],sm[1]), fmaxf(sm[2],sm[3]));
    const float e = __expf(v - m);
    float s = e;
    #pragma unroll
    for (int o = 16; o; o >>= 1) s += __shfl_xor_sync(0xffffffffu, s, o);
    if ((c & 31) == 0) sm2[c >> 5] = s;
    __syncthreads();
    s = sm2[0]+sm2[1]+sm2[2]+sm2[3];
    row[c] = e / s;
}

__global__ void cvec_k(const float* __restrict__ kn, const float* __restrict__ vn,
                       const float* __restrict__ inw, float* __restrict__ cst)
{
    const int t = threadIdx.x;
    const float* w = (t < 128) ? inw + 128*128 + (size_t)t*128
                               : inw + 256*128 + (size_t)(t-128)*128;
    const float* nz = (t < 128) ? kn : vn;
    float s = 0.f;
    #pragma unroll 8
    for (int j = 0; j < 128; ++j) s += nz[j] * w[j];
    cst[t] = s;
}

__global__ void combine_k(const float* __restrict__ QKV, const float* __restrict__ K1,
                          const float* __restrict__ V1, const float* __restrict__ CST,
                          float* __restrict__ OB)
{
    const int n = blockIdx.x, c = threadIdx.x;
    const float* qrow = QKV + (size_t)n * 384;
    const float qp  = qrow[c];
    const float kp0 = qrow[128 + c] + CST[c];
    const float kp1 = K1[(size_t)n * 128 + c];
    float s0 = qp * kp0, s1 = qp * kp1;
    #pragma unroll
    for (int o = 8; o; o >>= 1) {
        s0 += __shfl_xor_sync(0xffffffffu, s0, o, 16);
        s1 += __shfl_xor_sync(0xffffffffu, s1, o, 16);
    }
    s0 *= 0.25f; s1 *= 0.25f;
    const float m = fmaxf(s0, s1);
    const float e0 = __expf(s0 - m), e1 = __expf(s1 - m);
    const float inv = 1.0f / (e0 + e1);
    const float vp0 = qrow[256 + c] + CST[128 + c];
    const float vp1 = V1[(size_t)n * 128 + c];
    OB[(size_t)n * 128 + c] = e0 * inv * vp0 + e1 * inv * vp1;
}

extern "C" void kernel_launch(void* const* d_in, const int* in_sizes, int n_in,
                              void* d_out, int out_size)
{
    const float* x0        = (const float*)d_in[0];
    const float* x1        = (const float*)d_in[1];
    const float* Wq        = (const float*)d_in[2];
    const float* bq        = (const float*)d_in[3];
    const float* Wkv       = (const float*)d_in[4];
    const float* bkv       = (const float*)d_in[5];
    const float* sr_w      = (const float*)d_in[6];
    const float* sr_b      = (const float*)d_in[7];
    const float* ln0_g     = (const float*)d_in[8];
    const float* ln0_b     = (const float*)d_in[9];
    const float* ln1_g     = (const float*)d_in[10];
    const float* ln1_b     = (const float*)d_in[11];
    const float* ca01_in_w = (const float*)d_in[12];
    const float* ca01_in_b = (const float*)d_in[13];
    const float* ca01_out_w= (const float*)d_in[14];
    const float* ca01_out_b= (const float*)d_in[15];
    const float* ca10_in_w = (const float*)d_in[16];
    const float* ca10_in_b = (const float*)d_in[17];
    const float* ca10_out_w= (const float*)d_in[18];
    const float* ca10_out_b= (const float*)d_in[19];
    const float* rj_w1     = (const float*)d_in[20];
    const float* rj_b1     = (const float*)d_in[21];
    const float* rj_w2     = (const float*)d_in[22];
    const float* rj_b2     = (const float*)d_in[23];
    const float* k_noise   = (const float*)d_in[24];
    const float* v_noise   = (const float*)d_in[25];
    const float* proj_w    = (const float*)d_in[26];
    const float* proj_b    = (const float*)d_in[27];

    float* P = nullptr;
    cudaGetSymbolAddress((void**)&P, g_pool);
    float *XA0=P+OFF_XA0, *XA1=P+OFF_XA1, *Q=P+OFF_Q, *IM=P+OFF_IM, *PART=P+OFF_PART;
    float *WC=P+OFF_WC, *XILN=P+OFF_XILN, *KVB=P+OFF_KVB, *KH=P+OFF_KH, *VHT=P+OFF_VHT;
    float *SC=P+OFF_SC, *HB=P+OFF_HB, *SB=P+OFF_SB, *QKVB=P+OFF_QKV, *K1=P+OFF_K1;
    float *V1=P+OFF_V1, *OB=P+OFF_OB, *N0=P+OFF_N0, *N1=P+OFF_N1, *CST=P+OFF_CST;

    wconv_k<<<4096, 256>>>(sr_w, WC);
    im2col_k<<<2048, 256>>>(x0, x1, IM);

    // q projections (separate input buffers)
    tgemm_k<4,128,0,0><<<dim3(512,1,1), 256>>>(x0, nullptr, Wq, bq, nullptr, Q,          128, 128, 128, 0, 0);
    tgemm_k<4,128,0,0><<<dim3(512,1,1), 256>>>(x1, nullptr, Wq, bq, nullptr, Q + SZ,     128, 128, 128, 0, 0);

    // conv GEMM both streams, K-split 32 each
    tgemm_k<8,128,7,4><<<dim3(8,1,64), 256>>>(IM, nullptr, WC, nullptr, nullptr, PART, 8192, 8192, 128, 0, 0);
    convred_ln_k<<<2048, 128>>>(PART, sr_b, ln0_g, ln0_b, ln1_g, ln1_b, XILN);

    // kv projection both streams (2048 rows)
    tgemm_k<4,128,0,0><<<dim3(16,2,1), 256>>>(XILN, nullptr, Wkv, bkv, nullptr, KVB, 128, 128, 256, 0, 0);
    kvsplit_k<<<1024, 256>>>(KVB, KH, VHT);

    // SR attention both streams: z = s*8 + b*2 + h
    tgemm_k<2,128,3,4><<<dim3(128,2,16), 256>>>(Q, nullptr, KH, nullptr, nullptr, SC, 128, 64, 256, 0, 0);
    softmax256_k<<<32768, 256>>>(SC);
    tgemm_k<8,64,4,4><<<dim3(128,1,16), 256>>>(SC, nullptr, VHT, nullptr, nullptr, P /*XA0 base*/, 256, 256, 128, 0, 0);

    // judger both streams
    tgemm_k<8,128,6,1><<<dim3(512,1,2), 256>>>(XA0, XA1, rj_w1, rj_b1, nullptr, HB, 128, 256, 128, 0, SZ);
    tgemm_k<4,128,0,0><<<dim3(512,1,2), 256>>>(HB, nullptr, rj_w2, rj_b2, nullptr, SB, 128, 128, 128, SZ, SZ);
    softmax128_k<<<131072, 128>>>(SB);

    // mha2 per stream (stream-specific weights)
    for (int s = 0; s < 2; ++s) {
        const float* A  = s ? XA1 : XA0;
        const float* Bx = s ? XA0 : XA1;
        const float* inw = s ? ca10_in_w : ca01_in_w;
        const float* inb = s ? ca10_in_b : ca01_in_b;
        const float* ow  = s ? ca10_out_w : ca01_out_w;
        const float* ob  = s ? ca10_out_b : ca01_out_b;
        float* Nbuf = s ? N1 : N0;
        cvec_k<<<1, 256>>>(k_noise + s*128, v_noise + s*128, inw, CST);
        tgemm_k<4,128,0,0><<<dim3(512,3,1), 256>>>(A, nullptr, inw, inb, nullptr, QKVB, 128, 128, 384, 0, 0);
        tgemm_k<4,128,2,0><<<dim3(512,1,1), 256>>>(A, SB + s*SZ, inw + 128*128, inb + 128, nullptr, K1, 128, 128, 128, 0, 0);
        tgemm_k<4,128,0,0><<<dim3(512,1,1), 256>>>(Bx, nullptr, inw + 256*128, inb + 256, nullptr, V1, 128, 128, 128, 0, 0);
        combine_k<<<65536, 128>>>(QKVB, K1, V1, CST, OB);
        tgemm_k<4,128,0,2><<<dim3(512,1,1), 256>>>(OB, nullptr, ow, ob, A, Nbuf, 128, 128, 128, 0, 0);
    }

    // final projection, both streams (N0,N1 contiguous)
    float* out = (float*)d_out;
    tgemm_k<4,128,0,0><<<dim3(512,1,2), 256>>>(N0, nullptr, proj_w, proj_b, nullptr, out, 128, 128, 128, SZ, SZ);
}

// round 7
// speedup vs baseline: 2.9274x; 1.2347x over previous
#include <cuda_runtime.h>
#include <math.h>
#include <stdint.h>
#include <stddef.h>

#define NTOK 16384
#define CD   128
#define NB   65536
#define BMR  1024

static constexpr size_t SZ = (size_t)NB * CD;   // 8388608
static constexpr size_t OFF_XA0 = 0;
static constexpr size_t OFF_XA1 = SZ;
static constexpr size_t OFF_Q   = 2*SZ;          // 2 slices
static constexpr size_t OFF_PART= 4*SZ;          // 64*1024*128 == SZ
static constexpr size_t OFF_WC  = 5*SZ;
static constexpr size_t OFF_XILN= OFF_WC  + (size_t)CD*8192;
static constexpr size_t OFF_KVB = OFF_XILN+ (size_t)2*BMR*CD;
static constexpr size_t OFF_KH  = OFF_KVB + (size_t)2*BMR*2*CD;
static constexpr size_t OFF_VHT = OFF_KH  + (size_t)16*256*64;
static constexpr size_t OFF_SC  = OFF_VHT + (size_t)16*256*64;
static constexpr size_t OFF_HB  = OFF_SC  + 8*SZ;
static constexpr size_t OFF_SB  = OFF_HB  + 2*SZ;
static constexpr size_t OFF_QKV = OFF_SB  + 2*SZ;
static constexpr size_t OFF_K1  = OFF_QKV + 3*SZ;
static constexpr size_t OFF_V1  = OFF_K1  + SZ;
static constexpr size_t OFF_OB  = OFF_V1  + SZ;
static constexpr size_t OFF_N0  = OFF_OB  + SZ;
static constexpr size_t OFF_N1  = OFF_N0  + SZ;
static constexpr size_t OFF_CST = OFF_N1  + SZ;
static constexpr size_t POOL_SZ = OFF_CST + 256;

__device__ float g_pool[POOL_SZ];

__device__ __forceinline__ float geluf(float x) {
    return 0.5f * x * (1.0f + erff(x * 0.70710678118654752f));
}
__device__ __forceinline__ uint32_t f2tf32(float x) {
    uint32_t r; asm("cvt.rna.tf32.f32 %0, %1;" : "=r"(r) : "f"(x)); return r;
}
__device__ __forceinline__ uint32_t u2tf32(uint32_t u) {
    return f2tf32(__uint_as_float(u));
}
__device__ __forceinline__ void mma8(float* c, const uint32_t* a, const uint32_t* b) {
    asm volatile("mma.sync.aligned.m16n8k8.row.col.f32.tf32.tf32.f32 "
        "{%0,%1,%2,%3}, {%4,%5,%6,%7}, {%8,%9}, {%0,%1,%2,%3};"
        : "+f"(c[0]), "+f"(c[1]), "+f"(c[2]), "+f"(c[3])
        : "r"(a[0]), "r"(a[1]), "r"(a[2]), "r"(a[3]), "r"(b[0]), "r"(b[1]));
}
__device__ __forceinline__ void ldsm4(uint32_t* r, uint32_t addr) {
    asm volatile("ldmatrix.sync.aligned.m8n8.x4.shared.b16 {%0,%1,%2,%3}, [%4];"
        : "=r"(r[0]), "=r"(r[1]), "=r"(r[2]), "=r"(r[3]) : "r"(addr));
}
__device__ __forceinline__ void ldsm2(uint32_t* r, uint32_t addr) {
    asm volatile("ldmatrix.sync.aligned.m8n8.x2.shared.b16 {%0,%1}, [%2];"
        : "=r"(r[0]), "=r"(r[1]) : "r"(addr));
}
__device__ __forceinline__ void cpa16(uint32_t d, const void* s) {
    asm volatile("cp.async.cg.shared.global [%0], [%1], 16;" :: "r"(d), "l"(s));
}
__device__ __forceinline__ void cpcommit() { asm volatile("cp.async.commit_group;"); }
template<int N> __device__ __forceinline__ void cpwait() {
    asm volatile("cp.async.wait_group %0;" :: "n"(N));
}

// ---------------------------------------------------------------------------
// tf32 GEMM, tile BM x BN, BK=32, 8 warps, 2-stage cp.async pipeline,
// ldmatrix fragments with post-load tf32 conversion.
// AMODE: 0 plain (z via zsa/zso); 2 A0*A1; 3 SR scores; 4 SR PV;
//        5 dual plain (z picks A0/A1); 6 concat swap-by-z; 7 conv direct-x.
// EPI: 0 +bias; 1 +bias,gelu; 2 +bias,+res; 4 raw.  SMAX: row softmax over BN.
// ---------------------------------------------------------------------------
template<int BM, int BN, int KTILES, int AMODE, int EPI, int SMAX>
__global__ void __launch_bounds__(256, 2) tgemm_k(
    const float* __restrict__ A0, const float* __restrict__ A1,
    const float* __restrict__ W,  const float* __restrict__ bias,
    const float* __restrict__ res, float* __restrict__ out,
    int lda, int ldw, int ldo, size_t zsa, size_t zso)
{
    constexpr int PAD = 36;
    constexpr int colWarps = BN / 32;
    constexpr int rowWarps = 8 / colWarps;
    constexpr int WM = BM / rowWarps;
    constexpr int MT = WM / 16;
    constexpr int ACH = BM / 32;
    constexpr int WCH = BN / 32;
    constexpr int STG = (BM + BN) * PAD;          // floats per stage

    extern __shared__ float smem[];

    const int tid = threadIdx.x;
    const int w = tid >> 5, lane = tid & 31, g = lane >> 2, t = lane & 3;
    const int warpRow = w / colWarps, warpCol = w % colWarps;
    const int row0 = blockIdx.x * BM, col0 = blockIdx.y * BN;
    const int z = blockIdx.z;

    const float* Ap = A0 + z * zsa;
    const float* Aa = A0; const float* Ab = A1;
    const float* Wp = W;
    const float* Xs = A0;
    float* op = out + z * zso;
    int koff0 = 0;
    if (AMODE == 3) {
        Ap = A0 + (size_t)(z >> 3) * SZ + (size_t)((z >> 1) & 3) * (NTOK * 128) + (z & 1) * 64;
        Wp = W + (size_t)z * 16384;
        op = out + (size_t)z * NTOK * 256;
    } else if (AMODE == 4) {
        Ap = A0 + (size_t)z * NTOK * 256;
        Wp = W + (size_t)z * 16384;
        op = out + (size_t)(z >> 3) * SZ + (size_t)((z >> 1) & 3) * (NTOK * 128) + (z & 1) * 64;
    } else if (AMODE == 5) {
        Ap = z ? A1 : A0;
    } else if (AMODE == 6) {
        Aa = z ? A1 : A0; Ab = z ? A0 : A1;
    } else if (AMODE == 7) {
        Xs = (z >= 32) ? A1 : A0;
        koff0 = (z & 31) * (KTILES * 32);
    }

    const uint32_t smemB = (uint32_t)__cvta_generic_to_shared(smem);

    auto copy_tile = [&](int kt, int stage) {
        const int koff = koff0 + kt * 32;
        float* AsS = smem + stage * STG;
        const uint32_t aB = smemB + stage * STG * 4;
        const uint32_t wB = aB + BM * PAD * 4;
        #pragma unroll
        for (int i = 0; i < ACH; ++i) {
            const int fidx = i * 256 + tid;
            const int arow = fidx >> 3, kq = (fidx & 7) * 4;
            const int kg = koff + kq;
            if (AMODE == 2) {
                float4 a = *(const float4*)(A0 + (size_t)(row0 + arow) * lda + kg);
                float4 b = *(const float4*)(A1 + (size_t)(row0 + arow) * lda + kg);
                *(float4*)(AsS + arow * PAD + kq) = make_float4(a.x*b.x, a.y*b.y, a.z*b.z, a.w*b.w);
            } else {
                const float* src;
                if (AMODE == 6) {
                    src = (kg < 128) ? (Aa + (size_t)(row0 + arow) * 128 + kg)
                                     : (Ab + (size_t)(row0 + arow) * 128 + (kg - 128));
                } else if (AMODE == 7) {
                    const int gr = row0 + arow;
                    const int b_ = gr >> 8, p = gr & 255, ph = p >> 4, pw = p & 15;
                    const int ij = kg >> 7, c = kg & 127;
                    src = Xs + ((size_t)(b_ * 16384 + (ph*8 + (ij>>3)) * 128 + pw*8 + (ij&7))) * 128 + c;
                } else {
                    src = Ap + (size_t)(row0 + arow) * lda + kg;
                }
                cpa16(aB + (uint32_t)(arow * PAD + kq) * 4, src);
            }
        }
        #pragma unroll
        for (int i = 0; i < WCH; ++i) {
            const int fidx = i * 256 + tid;
            const int wrow = fidx >> 3, kq = (fidx & 7) * 4;
            cpa16(wB + (uint32_t)(wrow * PAD + kq) * 4,
                  Wp + (size_t)(col0 + wrow) * ldw + koff + kq);
        }
        cpcommit();
    };

    const int laneRowA = ((lane >> 3) & 1) * 8 + (lane & 7);
    const int laneKA   = (lane >> 4) * 4;
    const int laneRowB = lane & 7;
    const int laneKB   = ((lane >> 3) & 1) * 4;

    float acc[MT][4][4] = {};

    copy_tile(0, 0);
    for (int kt = 0; kt < KTILES; ++kt) {
        if (kt + 1 < KTILES) { copy_tile(kt + 1, (kt + 1) & 1); cpwait<1>(); }
        else cpwait<0>();
        __syncthreads();
        const uint32_t aB = smemB + (kt & 1) * STG * 4;
        const uint32_t wB = aB + BM * PAD * 4;
        #pragma unroll
        for (int k0 = 0; k0 < 32; k0 += 8) {
            uint32_t bf[4][2];
            #pragma unroll
            for (int nt = 0; nt < 4; ++nt) {
                ldsm2(bf[nt], wB + 4u * ((warpCol*32 + nt*8 + laneRowB) * PAD + laneKB + k0));
                bf[nt][0] = u2tf32(bf[nt][0]); bf[nt][1] = u2tf32(bf[nt][1]);
            }
            #pragma unroll
            for (int mt = 0; mt < MT; ++mt) {
                uint32_t af[4];
                ldsm4(af, aB + 4u * ((warpRow*WM + mt*16 + laneRowA) * PAD + laneKA + k0));
                af[0]=u2tf32(af[0]); af[1]=u2tf32(af[1]); af[2]=u2tf32(af[2]); af[3]=u2tf32(af[3]);
                #pragma unroll
                for (int nt = 0; nt < 4; ++nt) mma8(acc[mt][nt], af, bf[nt]);
            }
        }
        __syncthreads();
    }

    // bias
    if (EPI == 0 || EPI == 1 || EPI == 2) {
        #pragma unroll
        for (int nt = 0; nt < 4; ++nt) {
            const int cc = col0 + warpCol * 32 + nt * 8 + 2 * t;
            const float bx = bias[cc], by = bias[cc + 1];
            #pragma unroll
            for (int mt = 0; mt < MT; ++mt) {
                acc[mt][nt][0] += bx; acc[mt][nt][1] += by;
                acc[mt][nt][2] += bx; acc[mt][nt][3] += by;
            }
        }
    }

    if (SMAX) {
        float* redbuf = smem;          // BM * colWarps floats (smem free after loop)
        float rowmax[MT][2];
        #pragma unroll
        for (int mt = 0; mt < MT; ++mt)
            #pragma unroll
            for (int h = 0; h < 2; ++h) {
                float m = -3.4e38f;
                #pragma unroll
                for (int nt = 0; nt < 4; ++nt)
                    m = fmaxf(m, fmaxf(acc[mt][nt][h*2], acc[mt][nt][h*2+1]));
                m = fmaxf(m, __shfl_xor_sync(0xffffffffu, m, 1));
                m = fmaxf(m, __shfl_xor_sync(0xffffffffu, m, 2));
                const int rl = warpRow * WM + mt * 16 + g + h * 8;
                if (t == 0) redbuf[rl * colWarps + warpCol] = m;
                rowmax[mt][h] = m;
            }
        __syncthreads();
        #pragma unroll
        for (int mt = 0; mt < MT; ++mt)
            #pragma unroll
            for (int h = 0; h < 2; ++h) {
                const int rl = warpRow * WM + mt * 16 + g + h * 8;
                float m = -3.4e38f;
                #pragma unroll
                for (int cw = 0; cw < colWarps; ++cw)
                    m = fmaxf(m, redbuf[rl * colWarps + cw]);
                rowmax[mt][h] = m;
            }
        __syncthreads();
        #pragma unroll
        for (int mt = 0; mt < MT; ++mt)
            #pragma unroll
            for (int h = 0; h < 2; ++h) {
                float s = 0.f;
                #pragma unroll
                for (int nt = 0; nt < 4; ++nt) {
                    acc[mt][nt][h*2]   = __expf(acc[mt][nt][h*2]   - rowmax[mt][h]);
                    acc[mt][nt][h*2+1] = __expf(acc[mt][nt][h*2+1] - rowmax[mt][h]);
                    s += acc[mt][nt][h*2] + acc[mt][nt][h*2+1];
                }
                s += __shfl_xor_sync(0xffffffffu, s, 1);
                s += __shfl_xor_sync(0xffffffffu, s, 2);
                const int rl = warpRow * WM + mt * 16 + g + h * 8;
                if (t == 0) redbuf[rl * colWarps + warpCol] = s;
            }
        __syncthreads();
        #pragma unroll
        for (int mt = 0; mt < MT; ++mt)
            #pragma unroll
            for (int h = 0; h < 2; ++h) {
                const int rl = warpRow * WM + mt * 16 + g + h * 8;
                float s = 0.f;
                #pragma unroll
                for (int cw = 0; cw < colWarps; ++cw) s += redbuf[rl * colWarps + cw];
                const float inv = 1.0f / s;
                #pragma unroll
                for (int nt = 0; nt < 4; ++nt) {
                    acc[mt][nt][h*2] *= inv; acc[mt][nt][h*2+1] *= inv;
                }
            }
    }

    #pragma unroll
    for (int mt = 0; mt < MT; ++mt) {
        const int r = row0 + warpRow * WM + mt * 16 + g;
        #pragma unroll
        for (int nt = 0; nt < 4; ++nt) {
            const int cc = col0 + warpCol * 32 + nt * 8 + 2 * t;
            float v0 = acc[mt][nt][0], v1 = acc[mt][nt][1];
            float v2 = acc[mt][nt][2], v3 = acc[mt][nt][3];
            if (EPI == 1) { v0=geluf(v0); v1=geluf(v1); v2=geluf(v2); v3=geluf(v3); }
            if (EPI == 2) {
                float2 r0 = *(const float2*)(res + (size_t)r * ldo + cc);
                float2 r1 = *(const float2*)(res + (size_t)(r + 8) * ldo + cc);
                v0 += r0.x; v1 += r0.y; v2 += r1.x; v3 += r1.y;
            }
            *(float2*)(op + (size_t)r       * ldo + cc) = make_float2(v0, v1);
            *(float2*)(op + (size_t)(r + 8) * ldo + cc) = make_float2(v2, v3);
        }
    }
}

__global__ void wconv_k(const float* __restrict__ w, float* __restrict__ wc)
{
    const int idx = blockIdx.x * blockDim.x + threadIdx.x;
    if (idx >= CD * 8192) return;
    const int o = idx >> 13, k = idx & 8191, ij = k >> 7, c = k & 127;
    wc[idx] = w[(size_t)o * 8192 + c * 64 + ij];
}

__global__ void convred_ln_k(const float* __restrict__ part, const float* __restrict__ sb,
                             const float* __restrict__ g0, const float* __restrict__ b0,
                             const float* __restrict__ g1, const float* __restrict__ b1,
                             float* __restrict__ outp)
{
    const int row = blockIdx.x, c = threadIdx.x;       // 2048 x 128
    const int s = row >> 10, rl = row & 1023;
    const float* g  = s ? g1 : g0;
    const float* be = s ? b1 : b0;
    float v = sb[c];
    #pragma unroll
    for (int zz = 0; zz < 32; ++zz)
        v += part[(size_t)(s*32 + zz) * BMR * CD + (size_t)rl * CD + c];
    __shared__ float red[4], red2[4];
    float sum = v;
    #pragma unroll
    for (int o = 16; o; o >>= 1) sum += __shfl_xor_sync(0xffffffffu, sum, o);
    if ((c & 31) == 0) red[c >> 5] = sum;
    __syncthreads();
    const float mean = (red[0]+red[1]+red[2]+red[3]) * (1.0f/CD);
    const float d = v - mean;
    float s2 = d * d;
    #pragma unroll
    for (int o = 16; o; o >>= 1) s2 += __shfl_xor_sync(0xffffffffu, s2, o);
    if ((c & 31) == 0) red2[c >> 5] = s2;
    __syncthreads();
    const float var = (red2[0]+red2[1]+red2[2]+red2[3]) * (1.0f/CD);
    outp[(size_t)row * CD + c] = d * rsqrtf(var + 1e-5f) * g[c] + be[c];
}

__global__ void kvsplit_k(const float* __restrict__ KVb, float* __restrict__ Kh,
                          float* __restrict__ Vt)
{
    const int idx = blockIdx.x * blockDim.x + threadIdx.x;
    if (idx >= 16*256*64) return;
    const int zz = idx >> 14, r = idx & 16383, m = r >> 6, d = r & 63;
    const int s = zz >> 3, b = (zz >> 1) & 3, h = zz & 1;
    const float* src = KVb + ((size_t)(s*1024 + b*256 + m)) * 256 + h*64 + d;
    Kh[idx] = src[0] * 0.125f;
    Vt[(size_t)zz*16384 + d*256 + m] = src[128];
}

__global__ void cvec_k(const float* __restrict__ kn, const float* __restrict__ vn,
                       const float* __restrict__ inw, float* __restrict__ cst)
{
    const int t = threadIdx.x;
    const float* w = (t < 128) ? inw + 128*128 + (size_t)t*128
                               : inw + 256*128 + (size_t)(t-128)*128;
    const float* nz = (t < 128) ? kn : vn;
    float s = 0.f;
    #pragma unroll 8
    for (int j = 0; j < 128; ++j) s += nz[j] * w[j];
    cst[t] = s;
}

__global__ void combine_k(const float* __restrict__ QKV, const float* __restrict__ K1,
                          const float* __restrict__ V1, const float* __restrict__ CST,
                          float* __restrict__ OB)
{
    const int n = blockIdx.x, c = threadIdx.x;
    const float* qrow = QKV + (size_t)n * 384;
    const float qp  = qrow[c];
    const float kp0 = qrow[128 + c] + CST[c];
    const float kp1 = K1[(size_t)n * 128 + c];
    float s0 = qp * kp0, s1 = qp * kp1;
    #pragma unroll
    for (int o = 8; o; o >>= 1) {
        s0 += __shfl_xor_sync(0xffffffffu, s0, o, 16);
        s1 += __shfl_xor_sync(0xffffffffu, s1, o, 16);
    }
    s0 *= 0.25f; s1 *= 0.25f;
    const float m = fmaxf(s0, s1);
    const float e0 = __expf(s0 - m), e1 = __expf(s1 - m);
    const float inv = 1.0f / (e0 + e1);
    const float vp0 = qrow[256 + c] + CST[128 + c];
    const float vp1 = V1[(size_t)n * 128 + c];
    OB[(size_t)n * 128 + c] = e0 * inv * vp0 + e1 * inv * vp1;
}

extern "C" void kernel_launch(void* const* d_in, const int* in_sizes, int n_in,
                              void* d_out, int out_size)
{
    const float* x0        = (const float*)d_in[0];
    const float* x1        = (const float*)d_in[1];
    const float* Wq        = (const float*)d_in[2];
    const float* bq        = (const float*)d_in[3];
    const float* Wkv       = (const float*)d_in[4];
    const float* bkv       = (const float*)d_in[5];
    const float* sr_w      = (const float*)d_in[6];
    const float* sr_b      = (const float*)d_in[7];
    const float* ln0_g     = (const float*)d_in[8];
    const float* ln0_b     = (const float*)d_in[9];
    const float* ln1_g     = (const float*)d_in[10];
    const float* ln1_b     = (const float*)d_in[11];
    const float* ca01_in_w = (const float*)d_in[12];
    const float* ca01_in_b = (const float*)d_in[13];
    const float* ca01_out_w= (const float*)d_in[14];
    const float* ca01_out_b= (const float*)d_in[15];
    const float* ca10_in_w = (const float*)d_in[16];
    const float* ca10_in_b = (const float*)d_in[17];
    const float* ca10_out_w= (const float*)d_in[18];
    const float* ca10_out_b= (const float*)d_in[19];
    const float* rj_w1     = (const float*)d_in[20];
    const float* rj_b1     = (const float*)d_in[21];
    const float* rj_w2     = (const float*)d_in[22];
    const float* rj_b2     = (const float*)d_in[23];
    const float* k_noise   = (const float*)d_in[24];
    const float* v_noise   = (const float*)d_in[25];
    const float* proj_w    = (const float*)d_in[26];
    const float* proj_b    = (const float*)d_in[27];

    float* P = nullptr;
    cudaGetSymbolAddress((void**)&P, g_pool);
    float *XA0=P+OFF_XA0, *XA1=P+OFF_XA1, *Q=P+OFF_Q, *PART=P+OFF_PART;
    float *WC=P+OFF_WC, *XILN=P+OFF_XILN, *KVB=P+OFF_KVB, *KH=P+OFF_KH, *VHT=P+OFF_VHT;
    float *SC=P+OFF_SC, *HB=P+OFF_HB, *SB=P+OFF_SB, *QKVB=P+OFF_QKV, *K1=P+OFF_K1;
    float *V1=P+OFF_V1, *OB=P+OFF_OB, *N0=P+OFF_N0, *N1=P+OFF_N1, *CST=P+OFF_CST;

    constexpr int SM_128_128 = 2 * (128+128) * 36 * 4;   // 73728
    constexpr int SM_64_256  = 2 * (64+256)  * 36 * 4;   // 92160
    constexpr int SM_128_64  = 2 * (128+64)  * 36 * 4;   // 55296
    cudaFuncSetAttribute(tgemm_k<128,128,4,5,0,0>, cudaFuncAttributeMaxDynamicSharedMemorySize, SM_128_128);
    cudaFuncSetAttribute(tgemm_k<128,128,8,7,4,0>, cudaFuncAttributeMaxDynamicSharedMemorySize, SM_128_128);
    cudaFuncSetAttribute(tgemm_k<128,128,4,0,0,0>, cudaFuncAttributeMaxDynamicSharedMemorySize, SM_128_128);
    cudaFuncSetAttribute(tgemm_k<64,256,2,3,4,1>,  cudaFuncAttributeMaxDynamicSharedMemorySize, SM_64_256);
    cudaFuncSetAttribute(tgemm_k<128,64,8,4,4,0>,  cudaFuncAttributeMaxDynamicSharedMemorySize, SM_128_64);
    cudaFuncSetAttribute(tgemm_k<128,128,8,6,1,0>, cudaFuncAttributeMaxDynamicSharedMemorySize, SM_128_128);
    cudaFuncSetAttribute(tgemm_k<128,128,4,0,0,1>, cudaFuncAttributeMaxDynamicSharedMemorySize, SM_128_128);
    cudaFuncSetAttribute(tgemm_k<128,128,4,2,0,0>, cudaFuncAttributeMaxDynamicSharedMemorySize, SM_128_128);
    cudaFuncSetAttribute(tgemm_k<128,128,4,0,2,0>, cudaFuncAttributeMaxDynamicSharedMemorySize, SM_128_128);

    wconv_k<<<4096, 256>>>(sr_w, WC);

    // q projections, both streams (dual-A)
    tgemm_k<128,128,4,5,0,0><<<dim3(512,1,2), 256, SM_128_128>>>(
        x0, x1, Wq, bq, nullptr, Q, 128, 128, 128, 0, SZ);

    // conv GEMM direct from x, z = stream*32 + ksplit
    tgemm_k<128,128,8,7,4,0><<<dim3(8,1,64), 256, SM_128_128>>>(
        x0, x1, WC, nullptr, nullptr, PART, 8192, 8192, 128, 0, (size_t)BMR*CD);
    convred_ln_k<<<2048, 128>>>(PART, sr_b, ln0_g, ln0_b, ln1_g, ln1_b, XILN);

    // kv projection (2048 rows x 256 cols)
    tgemm_k<128,128,4,0,0,0><<<dim3(16,2,1), 256, SM_128_128>>>(
        XILN, nullptr, Wkv, bkv, nullptr, KVB, 128, 128, 256, 0, 0);
    kvsplit_k<<<1024, 256>>>(KVB, KH, VHT);

    // SR scores + fused softmax, z = s*8 + b*2 + h
    tgemm_k<64,256,2,3,4,1><<<dim3(256,1,16), 256, SM_64_256>>>(
        Q, nullptr, KH, nullptr, nullptr, SC, 128, 64, 256, 0, 0);
    // SR PV
    tgemm_k<128,64,8,4,4,0><<<dim3(128,1,16), 256, SM_128_64>>>(
        SC, nullptr, VHT, nullptr, nullptr, P /*XA0 base*/, 256, 256, 128, 0, 0);

    // judger: h (concat, gelu) then s (fused softmax), both streams
    tgemm_k<128,128,8,6,1,0><<<dim3(512,1,2), 256, SM_128_128>>>(
        XA0, XA1, rj_w1, rj_b1, nullptr, HB, 128, 256, 128, 0, SZ);
    tgemm_k<128,128,4,0,0,1><<<dim3(512,1,2), 256, SM_128_128>>>(
        HB, nullptr, rj_w2, rj_b2, nullptr, SB, 128, 128, 128, SZ, SZ);

    // mha2 per stream
    for (int s = 0; s < 2; ++s) {
        const float* A  = s ? XA1 : XA0;
        const float* Bx = s ? XA0 : XA1;
        const float* inw = s ? ca10_in_w : ca01_in_w;
        const float* inb = s ? ca10_in_b : ca01_in_b;
        const float* ow  = s ? ca10_out_w : ca01_out_w;
        const float* ob  = s ? ca10_out_b : ca01_out_b;
        float* Nbuf = s ? N1 : N0;
        cvec_k<<<1, 256>>>(k_noise + s*128, v_noise + s*128, inw, CST);
        tgemm_k<128,128,4,0,0,0><<<dim3(512,3,1), 256, SM_128_128>>>(
            A, nullptr, inw, inb, nullptr, QKVB, 128, 128, 384, 0, 0);
        tgemm_k<128,128,4,2,0,0><<<dim3(512,1,1), 256, SM_128_128>>>(
            A, SB + s*SZ, inw + 128*128, inb + 128, nullptr, K1, 128, 128, 128, 0, 0);
        tgemm_k<128,128,4,0,0,0><<<dim3(512,1,1), 256, SM_128_128>>>(
            Bx, nullptr, inw + 256*128, inb + 256, nullptr, V1, 128, 128, 128, 0, 0);
        combine_k<<<65536, 128>>>(QKVB, K1, V1, CST, OB);
        tgemm_k<128,128,4,0,2,0><<<dim3(512,1,1), 256, SM_128_128>>>(
            OB, nullptr, ow, ob, A, Nbuf, 128, 128, 128, 0, 0);
    }

    // final projection, both streams
    float* out = (float*)d_out;
    tgemm_k<128,128,4,0,0,0><<<dim3(512,1,2), 256, SM_128_128>>>(
        N0, nullptr, proj_w, proj_b, nullptr, out, 128, 128, 128, SZ, SZ);
}